// round 7
// baseline (speedup 1.0000x reference)
#include <cuda_runtime.h>
#include <math.h>

// Problem constants (from reference setup_inputs)
#define B 8
#define C 64
#define SPATIAL (48*48*48)        // 110592 floats per (b,c) channel
#define SPATIAL4 (SPATIAL/4)      // 27648 float4 per channel
#define SEG4 (SPATIAL4/2)         // 13824 float4 per half-row
#define NBLK 1024                 // 512 rows * 2 segments; also 64 rows * 16 chunks
#define CHUNK4 (SPATIAL4/16)      // 1728 float4 per gather chunk
#define R 8
#define NEG_SLOPE 0.01f

// Scratch (no cudaMalloc allowed)
__device__ float g_partials[NBLK];
__device__ int   g_arrive = 0;
__device__ int   g_done   = 0;

// ---------------------------------------------------------------------------
// One persistent kernel, three phases separated by a software grid barrier.
// 1024 blocks x 256 threads, forced 8 blocks/SM => all co-resident on 128+
// SMs (chip has 148+): the spin barrier cannot deadlock.
// ---------------------------------------------------------------------------
__global__ __launch_bounds__(256, 8) void fused_se_kernel(
    const float* __restrict__ x,
    const float* __restrict__ w1, const float* __restrict__ b1,
    const float* __restrict__ w2, const float* __restrict__ b2,
    float* __restrict__ out) {

    const int blk  = blockIdx.x;
    const int t    = threadIdx.x;
    const int lane = t & 31;
    const int wrp  = t >> 5;          // 0..7

    // ---------------- Phase A: half-row partial sums ----------------------
    {
        const int row = blk >> 1;     // 0..511
        const int seg = blk & 1;
        const float4* __restrict__ p =
            reinterpret_cast<const float4*>(x + (size_t)row * SPATIAL) + seg * SEG4;

        float ax = 0.f, ay = 0.f, az = 0.f, aw = 0.f;
        // 13824 / 256 = 54 iterations
#pragma unroll 6
        for (int i = t; i < SEG4; i += 256) {
            float4 v = p[i];
            ax += v.x; ay += v.y; az += v.z; aw += v.w;
        }
        float acc = (ax + ay) + (az + aw);

        for (int off = 16; off > 0; off >>= 1)
            acc += __shfl_down_sync(0xFFFFFFFFu, acc, off);

        __shared__ float warp_sums[8];
        if (lane == 0) warp_sums[wrp] = acc;
        __syncthreads();

        if (t == 0) {
            float s = warp_sums[0] + warp_sums[1] + warp_sums[2] + warp_sums[3]
                    + warp_sums[4] + warp_sums[5] + warp_sums[6] + warp_sums[7];
            g_partials[blk] = s;
        }
    }

    // ---------------- Grid barrier (co-resident, self-resetting) ----------
    if (t == 0) {
        __threadfence();                        // release partials
        atomicAdd(&g_arrive, 1);
        while (*(volatile int*)&g_arrive < NBLK) __nanosleep(128);
    }
    __syncthreads();
    __threadfence();                            // acquire partials

    // ---------------- Phase B: redundant per-block MLP + rank-r argmax ----
    __shared__ float mb[C];
    __shared__ float y1[C];
    __shared__ float y2[C];
    __shared__ int   ch_s;

    const int row64 = blk >> 4;       // 0..63 : b*R + r
    const int chunk = blk & 15;       // 0..15
    const int b = row64 >> 3;
    const int r = row64 & 7;

    if (t < C) {
        const float2 ps = reinterpret_cast<const float2*>(g_partials)[b * C + t];
        mb[t] = (ps.x + ps.y) * (1.0f / (float)SPATIAL);
    }
    __syncthreads();

    // layer 1: warp w -> channels 8w..8w+7 (coalesced weight LDG + shuffle)
    {
        const float m0 = mb[lane];
        const float m1 = mb[lane + 32];
#pragma unroll
        for (int c = 0; c < 8; c++) {
            const int i = 8 * wrp + c;
            const float* __restrict__ wr = w1 + i * C;
            float a = m0 * wr[lane] + m1 * wr[lane + 32];
#pragma unroll
            for (int off = 16; off > 0; off >>= 1)
                a += __shfl_down_sync(0xFFFFFFFFu, a, off);
            if (lane == 0) {
                a += b1[i];
                y1[i] = (a > 0.0f) ? a : NEG_SLOPE * a;
            }
        }
    }
    __syncthreads();

    // layer 2: same with w2, sigmoid
    {
        const float h0 = y1[lane];
        const float h1 = y1[lane + 32];
#pragma unroll
        for (int c = 0; c < 8; c++) {
            const int i = 8 * wrp + c;
            const float* __restrict__ wr = w2 + i * C;
            float a = h0 * wr[lane] + h1 * wr[lane + 32];
#pragma unroll
            for (int off = 16; off > 0; off >>= 1)
                a += __shfl_down_sync(0xFFFFFFFFu, a, off);
            if (lane == 0) {
                a += b2[i];
                y2[i] = 1.0f / (1.0f + expf(-a));
            }
        }
    }
    __syncthreads();

    // warp 0: r+1 rounds of warp-parallel argmax; strictly-greater wins,
    // ties keep the smaller index (matches jax.lax.top_k).
    if (t < 32) {
        float v0 = y2[t];
        float v1 = y2[t + 32];
        int sel = 0;
        for (int round = 0; round <= r; round++) {
            float bv; int bj;
            if (v0 >= v1) { bv = v0; bj = t; }
            else          { bv = v1; bj = t + 32; }
#pragma unroll
            for (int off = 16; off > 0; off >>= 1) {
                const float ov = __shfl_down_sync(0xFFFFFFFFu, bv, off);
                const int   oj = __shfl_down_sync(0xFFFFFFFFu, bj, off);
                if (ov > bv || (ov == bv && oj < bj)) { bv = ov; bj = oj; }
            }
            bj = __shfl_sync(0xFFFFFFFFu, bj, 0);
            sel = bj;
            if (bj == t)      v0 = -1.0f;   // sigmoid in (0,1)
            if (bj == t + 32) v1 = -1.0f;
        }
        if (t == 0) ch_s = sel;
    }
    __syncthreads();

    // ---------------- Phase C: copy this block's chunk of the channel -----
    {
        const int ch = ch_s;
        const float4* __restrict__ src =
            reinterpret_cast<const float4*>(x + ((size_t)b * C + ch) * SPATIAL)
            + chunk * CHUNK4;
        float4* __restrict__ dst =
            reinterpret_cast<float4*>(out) + (size_t)row64 * SPATIAL4
            + chunk * CHUNK4;

        // 1728 float4 = 6*256 + 192
#pragma unroll
        for (int k = 0; k < 7; k++) {
            const int i = k * 256 + t;
            if (i < CHUNK4) dst[i] = src[i];
        }
    }

    // ---------------- Reset barrier counters (last finisher) --------------
    if (t == 0) {
        const int d = atomicAdd(&g_done, 1);
        if (d == NBLK - 1) { g_arrive = 0; g_done = 0; }
    }
}

// ---------------------------------------------------------------------------
extern "C" void kernel_launch(void* const* d_in, const int* in_sizes, int n_in,
                              void* d_out, int out_size) {
    const float* x  = (const float*)d_in[0];
    const float* w1 = (const float*)d_in[1];
    const float* b1 = (const float*)d_in[2];
    const float* w2 = (const float*)d_in[3];
    const float* b2 = (const float*)d_in[4];
    float* out = (float*)d_out;

    fused_se_kernel<<<NBLK, 256>>>(x, w1, b1, w2, b2, out);
}

// round 8
// speedup vs baseline: 1.0708x; 1.0708x over previous
#include <cuda_runtime.h>
#include <math.h>

// Problem constants (from reference setup_inputs)
#define B 8
#define C 64
#define SPATIAL (48*48*48)        // 110592 floats per (b,c) channel
#define SPATIAL4 (SPATIAL/4)      // 27648 float4 per channel
#define SEGS 4                    // quarter-row segments
#define SEG4 (SPATIAL4/SEGS)      // 6912 float4 per segment
#define NBLK1 (B*C*SEGS)          // 2048 reduction blocks
#define R 8
#define NEG_SLOPE 0.01f

// gather kernel geometry: 6 chunks per row, 512 threads, 9 float4/thread
#define GT 512
#define GK 9
#define GBX 6                     // 6*512*9 = 27648 = SPATIAL4 exactly

// Scratch (no cudaMalloc allowed)
__device__ float g_partials[NBLK1];

// ---------------------------------------------------------------------------
// Kernel 1: quarter-row partial sums. 2048 blocks x 256 threads.
// ---------------------------------------------------------------------------
__global__ __launch_bounds__(256) void mean_partial_kernel(
    const float* __restrict__ x, float* __restrict__ partials) {
    const int blk = blockIdx.x;          // row*4 + seg
    const int row = blk >> 2;
    const int seg = blk & 3;
    const float4* __restrict__ p =
        reinterpret_cast<const float4*>(x + (size_t)row * SPATIAL) + seg * SEG4;

    float ax = 0.f, ay = 0.f, az = 0.f, aw = 0.f;
    // 6912 / 256 = 27 iterations
#pragma unroll 9
    for (int i = threadIdx.x; i < SEG4; i += 256) {
        float4 v = p[i];
        ax += v.x; ay += v.y; az += v.z; aw += v.w;
    }
    float acc = (ax + ay) + (az + aw);

    for (int off = 16; off > 0; off >>= 1)
        acc += __shfl_down_sync(0xFFFFFFFFu, acc, off);

    __shared__ float warp_sums[8];
    const int lane = threadIdx.x & 31;
    const int wid  = threadIdx.x >> 5;
    if (lane == 0) warp_sums[wid] = acc;
    __syncthreads();

    if (threadIdx.x == 0) {
        float s = warp_sums[0] + warp_sums[1] + warp_sums[2] + warp_sums[3]
                + warp_sums[4] + warp_sums[5] + warp_sums[6] + warp_sums[7];
        partials[blk] = s;
    }
}

// ---------------------------------------------------------------------------
// Kernel 2: gather fused with a redundant per-block warp-cooperative MLP.
// Warp w computes channels 4w..4w+3 per layer; lane l reads w[i*64+l] and
// w[i*64+32+l] straight from global (coalesced) -> 2 FMAs + shuffle reduce.
// Every block runs the identical FP sequence => deterministic.
// grid = (6, 64), 512 threads, 9 float4 copied per thread (exact cover).
// ---------------------------------------------------------------------------
__global__ __launch_bounds__(GT) void gather_mlp_kernel(
    const float* __restrict__ x,
    const float* __restrict__ w1, const float* __restrict__ b1,
    const float* __restrict__ w2, const float* __restrict__ b2,
    const float* __restrict__ partials,
    float* __restrict__ out) {

    __shared__ float mb[C];          // means for this batch
    __shared__ float y1[C];
    __shared__ float y2[C];
    __shared__ int   ch_s;

    const int row = blockIdx.y;      // 0..63 : b*R + r
    const int b   = row >> 3;
    const int r   = row & 7;
    const int t   = threadIdx.x;
    const int lane = t & 31;
    const int wrp  = t >> 5;         // 0..15

    // means: thread t<64 reduces the 4 quarter-row partials of channel t
    if (t < C) {
        float4 ps = reinterpret_cast<const float4*>(partials)[b * C + t];
        mb[t] = ((ps.x + ps.y) + (ps.z + ps.w)) * (1.0f / (float)SPATIAL);
    }
    __syncthreads();

    // layer 1: warp w -> channels 4w..4w+3
    {
        const float m0 = mb[lane];
        const float m1 = mb[lane + 32];
#pragma unroll
        for (int c = 0; c < 4; c++) {
            const int i = 4 * wrp + c;
            const float* __restrict__ wr = w1 + i * C;
            float a = m0 * wr[lane] + m1 * wr[lane + 32];
#pragma unroll
            for (int off = 16; off > 0; off >>= 1)
                a += __shfl_down_sync(0xFFFFFFFFu, a, off);
            if (lane == 0) {
                a += b1[i];
                y1[i] = (a > 0.0f) ? a : NEG_SLOPE * a;
            }
        }
    }
    __syncthreads();

    // layer 2: same pattern with w2, sigmoid
    {
        const float h0 = y1[lane];
        const float h1 = y1[lane + 32];
#pragma unroll
        for (int c = 0; c < 4; c++) {
            const int i = 4 * wrp + c;
            const float* __restrict__ wr = w2 + i * C;
            float a = h0 * wr[lane] + h1 * wr[lane + 32];
#pragma unroll
            for (int off = 16; off > 0; off >>= 1)
                a += __shfl_down_sync(0xFFFFFFFFu, a, off);
            if (lane == 0) {
                a += b2[i];
                y2[i] = 1.0f / (1.0f + expf(-a));
            }
        }
    }
    __syncthreads();

    // Warp 0: r+1 rounds of warp-parallel argmax over 64 channels.
    // Strictly-greater wins; ties keep the smaller index (jax top_k).
    if (t < 32) {
        float v0 = y2[t];
        float v1 = y2[t + 32];
        int sel = 0;
        for (int round = 0; round <= r; round++) {
            float bv; int bj;
            if (v0 >= v1) { bv = v0; bj = t; }        // tie -> smaller index
            else          { bv = v1; bj = t + 32; }
#pragma unroll
            for (int off = 16; off > 0; off >>= 1) {
                const float ov = __shfl_down_sync(0xFFFFFFFFu, bv, off);
                const int   oj = __shfl_down_sync(0xFFFFFFFFu, bj, off);
                if (ov > bv || (ov == bv && oj < bj)) { bv = ov; bj = oj; }
            }
            bj = __shfl_sync(0xFFFFFFFFu, bj, 0);
            sel = bj;
            if (bj == t)      v0 = -1.0f;             // sigmoid in (0,1)
            if (bj == t + 32) v1 = -1.0f;
        }
        if (t == 0) ch_s = sel;
    }
    __syncthreads();

    // Copy the selected channel: 9 float4 per thread, coalesced, exact cover.
    const int ch = ch_s;
    const float4* __restrict__ src =
        reinterpret_cast<const float4*>(x + ((size_t)b * C + ch) * SPATIAL);
    float4* __restrict__ dst =
        reinterpret_cast<float4*>(out) + (size_t)row * SPATIAL4;

#pragma unroll
    for (int k = 0; k < GK; k++) {
        const int i = (blockIdx.x * GK + k) * GT + t;  // 0..27647
        dst[i] = src[i];
    }
}

// ---------------------------------------------------------------------------
extern "C" void kernel_launch(void* const* d_in, const int* in_sizes, int n_in,
                              void* d_out, int out_size) {
    const float* x  = (const float*)d_in[0];
    const float* w1 = (const float*)d_in[1];
    const float* b1 = (const float*)d_in[2];
    const float* w2 = (const float*)d_in[3];
    const float* b2 = (const float*)d_in[4];
    float* out = (float*)d_out;

    float* partials;
    cudaGetSymbolAddress((void**)&partials, g_partials);

    mean_partial_kernel<<<NBLK1, 256>>>(x, partials);
    dim3 grid(GBX, B * R);   // (6, 64)
    gather_mlp_kernel<<<grid, GT>>>(x, w1, b1, w2, b2, partials, out);
}